// round 3
// baseline (speedup 1.0000x reference)
#include <cuda_runtime.h>
#include <cuda_bf16.h>
#include <math.h>

// Shapes (fixed by the problem)
#define BB      2
#define TT_SEQ  1024
#define DM      768
#define DI      1536        // D_INNER
#define DS      16          // D_STATE
#define DR      48          // DT_RANK
#define TOK     (BB*TT_SEQ) // 2048
#define XPROJ_N (DR + 2*DS) // 80

// -------- device scratch (no allocs allowed) --------
__device__ float g_h   [TOK * DM];        // layernorm output
__device__ float g_xz  [TOK * 2 * DI];    // h @ W_in^T
__device__ float g_xc  [TOK * DI];        // conv + silu
__device__ float g_xdbl[TOK * XPROJ_N];   // xc @ W_xproj^T
__device__ float g_dt  [TOK * DI];        // softplus(dt_r @ W_dt^T + b_dt)
__device__ float g_y   [TOK * DI];        // scan output, gated

// ---------------------------------------------------------------------------
// Block reduce (256 threads)
// ---------------------------------------------------------------------------
__device__ __forceinline__ float blockReduce256(float v, float* sh) {
    __syncthreads();
    int lane = threadIdx.x & 31, w = threadIdx.x >> 5;
#pragma unroll
    for (int o = 16; o; o >>= 1) v += __shfl_xor_sync(0xffffffffu, v, o);
    if (lane == 0) sh[w] = v;
    __syncthreads();
    float r = sh[0];
#pragma unroll
    for (int i = 1; i < 8; i++) r += sh[i];
    return r;
}

// ---------------------------------------------------------------------------
// LayerNorm: one block per token row (768 cols, 256 threads x 3)
// ---------------------------------------------------------------------------
__global__ void __launch_bounds__(256) ln_kernel(
    const float* __restrict__ x, const float* __restrict__ g,
    const float* __restrict__ bta, float* __restrict__ h)
{
    __shared__ float sh[8];
    int row = blockIdx.x;
    int tid = threadIdx.x;
    const float* xr = x + (size_t)row * DM;
    float v[3]; float sum = 0.f;
#pragma unroll
    for (int i = 0; i < 3; i++) { v[i] = xr[tid + i*256]; sum += v[i]; }
    sum = blockReduce256(sum, sh);
    float mu = sum * (1.f/768.f);
    float q = 0.f;
#pragma unroll
    for (int i = 0; i < 3; i++) { float d = v[i]-mu; q += d*d; }
    q = blockReduce256(q, sh);
    float rs = rsqrtf(q * (1.f/768.f) + 1e-5f);
    float* hr = h + (size_t)row * DM;
#pragma unroll
    for (int i = 0; i < 3; i++) {
        int c = tid + i*256;
        hr[c] = (v[i]-mu) * rs * g[c] + bta[c];
    }
}

// ---------------------------------------------------------------------------
// Generic C = A(MxK, lda) * B(NxK, ldb)^T, tiled SGEMM.
// Block = 256 threads (16x16). BM=16*TM, BN=16*TN, BK=16.
// MODE 0: store. MODE 1: softplus(acc + ep[col]). MODE 2: acc + ep[row*N+col].
// Requires M % BM == 0 and K % 16 == 0 (true for all call sites).
// ---------------------------------------------------------------------------
__device__ __forceinline__ float softplus_f(float v) {
    return (v > 20.f) ? v : log1pf(__expf(v));
}

template<int TM, int TN, int MODE>
__global__ void __launch_bounds__(256) gemm_tn_kernel(
    const float* __restrict__ A, int lda,
    const float* __restrict__ B, int ldb,
    float* __restrict__ C,
    const float* __restrict__ ep,
    int M, int N, int K)
{
    constexpr int BM = 16*TM, BN = 16*TN, BK = 16;
    __shared__ float As[BK][BM+1];
    __shared__ float Bs[BK][BN+1];
    const int tid = threadIdx.x;
    const int tx = tid & 15, ty = tid >> 4;
    const int m0 = blockIdx.y * BM, n0 = blockIdx.x * BN;

    float acc[TM][TN];
#pragma unroll
    for (int i = 0; i < TM; i++)
#pragma unroll
        for (int j = 0; j < TN; j++) acc[i][j] = 0.f;

    for (int k0 = 0; k0 < K; k0 += BK) {
#pragma unroll
        for (int i = 0; i < TM; i++) {
            int e = tid + i*256; int r = e >> 4, c = e & 15;
            As[c][r] = A[(size_t)(m0 + r) * lda + k0 + c];
        }
#pragma unroll
        for (int i = 0; i < TN; i++) {
            int e = tid + i*256; int r = e >> 4, c = e & 15;
            int n = n0 + r;
            Bs[c][r] = (n < N) ? B[(size_t)n * ldb + k0 + c] : 0.f;
        }
        __syncthreads();
#pragma unroll
        for (int kk = 0; kk < BK; kk++) {
            float a[TM], bb[TN];
#pragma unroll
            for (int i = 0; i < TM; i++) a[i] = As[kk][ty + 16*i];
#pragma unroll
            for (int j = 0; j < TN; j++) bb[j] = Bs[kk][tx + 16*j];
#pragma unroll
            for (int i = 0; i < TM; i++)
#pragma unroll
                for (int j = 0; j < TN; j++)
                    acc[i][j] = fmaf(a[i], bb[j], acc[i][j]);
        }
        __syncthreads();
    }

#pragma unroll
    for (int i = 0; i < TM; i++) {
        int row = m0 + ty + 16*i;
#pragma unroll
        for (int j = 0; j < TN; j++) {
            int col = n0 + tx + 16*j;
            if (col < N) {
                float v = acc[i][j];
                if (MODE == 1) v = softplus_f(v + ep[col]);
                if (MODE == 2) v += ep[(size_t)row * N + col];
                C[(size_t)row * N + col] = v;
            }
        }
    }
}

// ---------------------------------------------------------------------------
// Depthwise causal conv (width 4) + bias + SiLU on xs = xz[:, :DI]
// ---------------------------------------------------------------------------
__global__ void __launch_bounds__(256) conv_silu_kernel(
    const float* __restrict__ xz, const float* __restrict__ w,
    const float* __restrict__ b, float* __restrict__ xc)
{
    int idx = blockIdx.x * 256 + threadIdx.x;        // over BB*T*DI
    int d = idx % DI;
    int t = (idx / DI) % TT_SEQ;
    int bb = idx / (DI * TT_SEQ);
    const float* xs = xz + (size_t)bb * TT_SEQ * (2*DI);
    float acc = b[d];
#pragma unroll
    for (int k = 0; k < 4; k++) {
        int tt = t - 3 + k;
        if (tt >= 0) acc = fmaf(w[d*4 + k], xs[(size_t)tt * (2*DI) + d], acc);
    }
    float s = acc / (1.f + __expf(-acc));            // silu
    xc[(size_t)(bb * TT_SEQ + t) * DI + d] = s;
}

// ---------------------------------------------------------------------------
// Selective scan. Block = 256 threads = 16 channels x 16 states.
// Grid = (DI/16, BB). Fuses: dA=exp(dt*A), dBu, recurrence, C-reduction,
// D skip, SiLU(z) gate. Time chunked through shared memory.
// ---------------------------------------------------------------------------
__global__ void __launch_bounds__(256) scan_kernel(
    const float* __restrict__ dt, const float* __restrict__ xc,
    const float* __restrict__ xz, const float* __restrict__ xdbl,
    const float* __restrict__ A_log, const float* __restrict__ Dp,
    float* __restrict__ y)
{
    constexpr int CH = 64;  // time chunk
    __shared__ float dt_s[CH][16], xc_s[CH][16], z_s[CH][16];
    __shared__ float B_s[CH][16], C_s[CH][16], y_s[CH][16];

    const int b  = blockIdx.y;
    const int d0 = blockIdx.x * 16;
    const int tid = threadIdx.x;
    const int n  = tid & 15;      // state index
    const int dl = tid >> 4;      // local channel
    const int d  = d0 + dl;

    const float A_dn = -__expf(A_log[d * DS + n]);
    const float Dpd  = Dp[d];
    float s = 0.f;
    const size_t base = (size_t)b * TT_SEQ;

    for (int t0 = 0; t0 < TT_SEQ; t0 += CH) {
#pragma unroll
        for (int i = 0; i < 4; i++) {
            int e = tid + i*256; int tt = e >> 4, j = e & 15;
            size_t row = base + t0 + tt;
            dt_s[tt][j] = dt[row * DI + d0 + j];
            xc_s[tt][j] = xc[row * DI + d0 + j];
            z_s[tt][j]  = xz[row * (2*DI) + DI + d0 + j];
            B_s[tt][j]  = xdbl[row * XPROJ_N + DR + j];
            C_s[tt][j]  = xdbl[row * XPROJ_N + DR + DS + j];
        }
        __syncthreads();
        for (int t = 0; t < CH; t++) {
            float dtv = dt_s[t][dl];
            float xcv = xc_s[t][dl];
            float dA  = __expf(A_dn * dtv);
            s = fmaf(dA, s, dtv * xcv * B_s[t][n]);
            float p = s * C_s[t][n];
            p += __shfl_xor_sync(0xffffffffu, p, 8, 16);
            p += __shfl_xor_sync(0xffffffffu, p, 4, 16);
            p += __shfl_xor_sync(0xffffffffu, p, 2, 16);
            p += __shfl_xor_sync(0xffffffffu, p, 1, 16);
            if (n == 0) {
                float zv = z_s[t][dl];
                float sil = zv / (1.f + __expf(-zv));
                y_s[t][dl] = (p + Dpd * xcv) * sil;
            }
        }
        __syncthreads();
#pragma unroll
        for (int i = 0; i < 4; i++) {
            int e = tid + i*256; int tt = e >> 4, j = e & 15;
            y[(base + t0 + tt) * DI + d0 + j] = y_s[tt][j];
        }
        __syncthreads();
    }
}

// ---------------------------------------------------------------------------
// Launch
// ---------------------------------------------------------------------------
extern "C" void kernel_launch(void* const* d_in, const int* in_sizes, int n_in,
                              void* d_out, int out_size)
{
    const float* x      = (const float*)d_in[0];
    const float* ln_g   = (const float*)d_in[1];
    const float* ln_b   = (const float*)d_in[2];
    const float* W_in   = (const float*)d_in[3];
    const float* conv_w = (const float*)d_in[4];
    const float* conv_b = (const float*)d_in[5];
    const float* W_xprj = (const float*)d_in[6];
    const float* W_dt   = (const float*)d_in[7];
    const float* b_dt   = (const float*)d_in[8];
    const float* A_log  = (const float*)d_in[9];
    const float* Dp     = (const float*)d_in[10];
    const float* W_out  = (const float*)d_in[11];
    float* out = (float*)d_out;

    float *h, *xz, *xc, *xdbl, *dt, *y;
    cudaGetSymbolAddress((void**)&h,    g_h);
    cudaGetSymbolAddress((void**)&xz,   g_xz);
    cudaGetSymbolAddress((void**)&xc,   g_xc);
    cudaGetSymbolAddress((void**)&xdbl, g_xdbl);
    cudaGetSymbolAddress((void**)&dt,   g_dt);
    cudaGetSymbolAddress((void**)&y,    g_y);

    // 1. LayerNorm
    ln_kernel<<<TOK, 256>>>(x, ln_g, ln_b, h);

    // 2. xz = h @ W_in^T   (2048 x 3072 x 768)
    gemm_tn_kernel<4,8,0><<<dim3((2*DI)/128, TOK/64), 256>>>(
        h, DM, W_in, DM, xz, nullptr, TOK, 2*DI, DM);

    // 3. depthwise conv + silu -> xc
    conv_silu_kernel<<<(TOK*DI)/256, 256>>>(xz, conv_w, conv_b, xc);

    // 4. x_dbl = xc @ W_xproj^T  (2048 x 80 x 1536)
    gemm_tn_kernel<2,2,0><<<dim3((XPROJ_N + 31)/32, TOK/32), 256>>>(
        xc, DI, W_xprj, DI, xdbl, nullptr, TOK, XPROJ_N, DI);

    // 5. dt = softplus(dt_r @ W_dt^T + b_dt)  (2048 x 1536 x 48)
    gemm_tn_kernel<4,8,1><<<dim3(DI/128, TOK/64), 256>>>(
        xdbl, XPROJ_N, W_dt, DR, dt, b_dt, TOK, DI, DR);

    // 6. selective scan -> y (gated)
    scan_kernel<<<dim3(DI/16, BB), 256>>>(dt, xc, xz, xdbl, A_log, Dp, y);

    // 7. out = x + y @ W_out^T  (2048 x 768 x 1536)
    gemm_tn_kernel<4,8,2><<<dim3(DM/128, TOK/64), 256>>>(
        y, DI, W_out, DI, out, x, TOK, DM, DI);
}

// round 5
// speedup vs baseline: 2.2012x; 2.2012x over previous
#include <cuda_runtime.h>
#include <cuda_bf16.h>
#include <math.h>
#include <stdint.h>

// Shapes (fixed by the problem)
#define BB      2
#define TT_SEQ  1024
#define DM      768
#define DI      1536        // D_INNER
#define DS      16          // D_STATE
#define DR      48          // DT_RANK
#define TOK     (BB*TT_SEQ) // 2048
#define XPROJ_N (DR + 2*DS) // 80
#define KSPLIT  8
#define PART_STRIDE (TOK * XPROJ_N)   // 163840

// -------- device scratch (no allocs allowed) --------
__device__ float g_h        [TOK * DM];
__device__ float g_xz       [TOK * 2 * DI];
__device__ float g_xc       [TOK * DI];
__device__ float g_xdbl     [TOK * XPROJ_N];
__device__ float g_xdbl_part[KSPLIT * PART_STRIDE];
__device__ float g_dt       [TOK * DI];
__device__ float g_y        [TOK * DI];

// ===========================================================================
// Helpers
// ===========================================================================
__device__ __forceinline__ uint32_t smem_u32(const void* p) {
    uint32_t a;
    asm("{ .reg .u64 t; cvta.to.shared.u64 t, %1; cvt.u32.u64 %0, t; }"
        : "=r"(a) : "l"(p));
    return a;
}
__device__ __forceinline__ void cp16(uint32_t dst, const void* src, int bytes) {
    asm volatile("cp.async.cg.shared.global [%0], [%1], 16, %2;"
                 :: "r"(dst), "l"(src), "r"(bytes) : "memory");
}
#define CP_COMMIT() asm volatile("cp.async.commit_group;" ::: "memory")
#define CP_WAIT(n)  asm volatile("cp.async.wait_group %0;" :: "n"(n) : "memory")

__device__ __forceinline__ void mma_tf32(float* c, const uint32_t* a, const uint32_t* b) {
    asm volatile(
        "mma.sync.aligned.m16n8k8.row.col.f32.tf32.tf32.f32 "
        "{%0,%1,%2,%3}, {%4,%5,%6,%7}, {%8,%9}, {%0,%1,%2,%3};"
        : "+f"(c[0]), "+f"(c[1]), "+f"(c[2]), "+f"(c[3])
        : "r"(a[0]), "r"(a[1]), "r"(a[2]), "r"(a[3]), "r"(b[0]), "r"(b[1]));
}

__device__ __forceinline__ float softplus_f(float v) {
    return (v > 20.f) ? v : log1pf(__expf(v));
}

// ===========================================================================
// tf32 mma.sync GEMM: C = A(M x K, lda) * B(N x K, ldb)^T
// Block tile 128x128, BK=32, 256 threads = 8 warps (4 M x 2 N), warp 32x64.
// Shared: As[128][36], Bs[128][36] per buffer, 2 buffers (cp.async pipeline).
// Grid: x = N tile, y = M tile, z = K split.
// MODE 0: store. MODE 1: softplus(acc + ep[col]). MODE 2: acc + ep[row*ldc+col].
// Requires M % 128 == 0 and N % 8 == 0 (true at all call sites).
// ===========================================================================
#define PITCH 36
#define TILE_ELEMS (128 * PITCH)            // floats per matrix tile
#define BUF_ELEMS  (2 * TILE_ELEMS)         // A + B
#define GEMM_SMEM_BYTES (2 * BUF_ELEMS * 4) // 73728

template<int MODE>
__global__ void __launch_bounds__(256) gemm_mma_kernel(
    const float* __restrict__ A, int lda,
    const float* __restrict__ B, int ldb,
    float* __restrict__ C, int ldc,
    const float* __restrict__ ep,
    int N, int Ktotal, int ksplit, size_t zstride)
{
    extern __shared__ float smem[];
    const int tid = threadIdx.x;
    const int wid = tid >> 5, lid = tid & 31;
    const int g = lid >> 2, tig = lid & 3;
    const int warp_m = (wid & 3) * 32;
    const int warp_n = (wid >> 2) * 64;
    const int m0 = blockIdx.y * 128;
    const int n0 = blockIdx.x * 128;
    const int kbeg = blockIdx.z * ksplit;
    const int kend = min(kbeg + ksplit, Ktotal);
    C += (size_t)blockIdx.z * zstride;

    const uint32_t sbase = smem_u32(smem);

    float acc[2][8][4];
#pragma unroll
    for (int i = 0; i < 2; i++)
#pragma unroll
        for (int j = 0; j < 8; j++)
#pragma unroll
            for (int q = 0; q < 4; q++) acc[i][j][q] = 0.f;

    const int NT = (kend - kbeg + 31) >> 5;

    // tile loader: global -> smem buffer (cp.async, zero-filled edges)
    auto load_tiles = [&](int it, int buf) {
        const int k0 = kbeg + it * 32;
        const uint32_t sA = sbase + (uint32_t)(buf * BUF_ELEMS) * 4;
        const uint32_t sB = sA + (uint32_t)TILE_ELEMS * 4;
#pragma unroll
        for (int j = 0; j < 4; j++) {
            int idx = tid + j * 256;           // 0..1023
            int r = idx >> 3, c4 = (idx & 7) * 4;
            int kk = k0 + c4;
            int bytes = min(max(kend - kk, 0), 4) * 4;
            int ksafe = bytes ? kk : k0;
            // A tile row m0+r (always valid)
            cp16(sA + (uint32_t)(r * PITCH + c4) * 4,
                 A + (size_t)(m0 + r) * lda + ksafe, bytes);
            // B tile row n0+r (guard N)
            int nr = n0 + r;
            int bytesB = (nr < N) ? bytes : 0;
            cp16(sB + (uint32_t)(r * PITCH + c4) * 4,
                 B + (size_t)((nr < N) ? nr : 0) * ldb + ksafe, bytesB);
        }
        CP_COMMIT();
    };

    load_tiles(0, 0);

    for (int it = 0; it < NT; it++) {
        if (it + 1 < NT) { load_tiles(it + 1, (it + 1) & 1); CP_WAIT(1); }
        else             { CP_WAIT(0); }
        __syncthreads();

        const float* As = smem + (it & 1) * BUF_ELEMS;
        const float* Bs = As + TILE_ELEMS;
#pragma unroll
        for (int ks = 0; ks < 4; ks++) {
            const int k = ks * 8;
            uint32_t a[2][4], b[8][2];
#pragma unroll
            for (int ma = 0; ma < 2; ma++) {
                int r = warp_m + ma * 16 + g;
                a[ma][0] = __float_as_uint(As[r * PITCH + k + tig]);
                a[ma][1] = __float_as_uint(As[(r + 8) * PITCH + k + tig]);
                a[ma][2] = __float_as_uint(As[r * PITCH + k + tig + 4]);
                a[ma][3] = __float_as_uint(As[(r + 8) * PITCH + k + tig + 4]);
            }
#pragma unroll
            for (int na = 0; na < 8; na++) {
                int rn = warp_n + na * 8 + g;
                b[na][0] = __float_as_uint(Bs[rn * PITCH + k + tig]);
                b[na][1] = __float_as_uint(Bs[rn * PITCH + k + tig + 4]);
            }
#pragma unroll
            for (int ma = 0; ma < 2; ma++)
#pragma unroll
                for (int na = 0; na < 8; na++)
                    mma_tf32(acc[ma][na], a[ma], b[na]);
        }
        __syncthreads();
    }

    // Epilogue: c0,c1 -> (row g, col tig*2 +0/1); c2,c3 -> row g+8
#pragma unroll
    for (int ma = 0; ma < 2; ma++) {
        int row0 = m0 + warp_m + ma * 16 + g;
#pragma unroll
        for (int na = 0; na < 8; na++) {
            int col = n0 + warp_n + na * 8 + tig * 2;
            if (col < N) {
                float v0 = acc[ma][na][0], v1 = acc[ma][na][1];
                float v2 = acc[ma][na][2], v3 = acc[ma][na][3];
                if (MODE == 1) {
                    v0 = softplus_f(v0 + ep[col]);  v1 = softplus_f(v1 + ep[col+1]);
                    v2 = softplus_f(v2 + ep[col]);  v3 = softplus_f(v3 + ep[col+1]);
                }
                if (MODE == 2) {
                    const float2 e0 = *(const float2*)&ep[(size_t)row0 * ldc + col];
                    const float2 e1 = *(const float2*)&ep[(size_t)(row0+8) * ldc + col];
                    v0 += e0.x; v1 += e0.y; v2 += e1.x; v3 += e1.y;
                }
                *(float2*)&C[(size_t)row0 * ldc + col]       = make_float2(v0, v1);
                *(float2*)&C[(size_t)(row0 + 8) * ldc + col] = make_float2(v2, v3);
            }
        }
    }
}

// ===========================================================================
// Split-K reduction for x_dbl (deterministic)
// ===========================================================================
__global__ void __launch_bounds__(256) reduce_ksplit_kernel(
    const float* __restrict__ part, float* __restrict__ o)
{
    int i = blockIdx.x * 256 + threadIdx.x;
    float s = 0.f;
#pragma unroll
    for (int z = 0; z < KSPLIT; z++) s += part[(size_t)z * PART_STRIDE + i];
    o[i] = s;
}

// ===========================================================================
// Block reduce (256 threads)
// ===========================================================================
__device__ __forceinline__ float blockReduce256(float v, float* sh) {
    __syncthreads();
    int lane = threadIdx.x & 31, w = threadIdx.x >> 5;
#pragma unroll
    for (int o = 16; o; o >>= 1) v += __shfl_xor_sync(0xffffffffu, v, o);
    if (lane == 0) sh[w] = v;
    __syncthreads();
    float r = sh[0];
#pragma unroll
    for (int i = 1; i < 8; i++) r += sh[i];
    return r;
}

// ---------------------------------------------------------------------------
// LayerNorm
// ---------------------------------------------------------------------------
__global__ void __launch_bounds__(256) ln_kernel(
    const float* __restrict__ x, const float* __restrict__ g,
    const float* __restrict__ bta, float* __restrict__ h)
{
    __shared__ float sh[8];
    int row = blockIdx.x;
    int tid = threadIdx.x;
    const float* xr = x + (size_t)row * DM;
    float v[3]; float sum = 0.f;
#pragma unroll
    for (int i = 0; i < 3; i++) { v[i] = xr[tid + i*256]; sum += v[i]; }
    sum = blockReduce256(sum, sh);
    float mu = sum * (1.f/768.f);
    float q = 0.f;
#pragma unroll
    for (int i = 0; i < 3; i++) { float d = v[i]-mu; q += d*d; }
    q = blockReduce256(q, sh);
    float rs = rsqrtf(q * (1.f/768.f) + 1e-5f);
    float* hr = h + (size_t)row * DM;
#pragma unroll
    for (int i = 0; i < 3; i++) {
        int c = tid + i*256;
        hr[c] = (v[i]-mu) * rs * g[c] + bta[c];
    }
}

// ---------------------------------------------------------------------------
// Depthwise causal conv (width 4) + bias + SiLU
// ---------------------------------------------------------------------------
__global__ void __launch_bounds__(256) conv_silu_kernel(
    const float* __restrict__ xz, const float* __restrict__ w,
    const float* __restrict__ b, float* __restrict__ xc)
{
    int idx = blockIdx.x * 256 + threadIdx.x;
    int d = idx % DI;
    int t = (idx / DI) % TT_SEQ;
    int bb = idx / (DI * TT_SEQ);
    const float* xs = xz + (size_t)bb * TT_SEQ * (2*DI);
    float acc = b[d];
#pragma unroll
    for (int k = 0; k < 4; k++) {
        int tt = t - 3 + k;
        if (tt >= 0) acc = fmaf(w[d*4 + k], xs[(size_t)tt * (2*DI) + d], acc);
    }
    float s = acc / (1.f + __expf(-acc));
    xc[(size_t)(bb * TT_SEQ + t) * DI + d] = s;
}

// ---------------------------------------------------------------------------
// Selective scan (16 channels x 16 states per block)
// ---------------------------------------------------------------------------
__global__ void __launch_bounds__(256) scan_kernel(
    const float* __restrict__ dt, const float* __restrict__ xc,
    const float* __restrict__ xz, const float* __restrict__ xdbl,
    const float* __restrict__ A_log, const float* __restrict__ Dp,
    float* __restrict__ y)
{
    constexpr int CH = 64;
    __shared__ float dt_s[CH][16], xc_s[CH][16], z_s[CH][16];
    __shared__ float B_s[CH][16], C_s[CH][16], y_s[CH][16];

    const int b  = blockIdx.y;
    const int d0 = blockIdx.x * 16;
    const int tid = threadIdx.x;
    const int n  = tid & 15;
    const int dl = tid >> 4;
    const int d  = d0 + dl;

    const float A_dn = -__expf(A_log[d * DS + n]);
    const float Dpd  = Dp[d];
    float s = 0.f;
    const size_t base = (size_t)b * TT_SEQ;

    for (int t0 = 0; t0 < TT_SEQ; t0 += CH) {
#pragma unroll
        for (int i = 0; i < 4; i++) {
            int e = tid + i*256; int tt = e >> 4, j = e & 15;
            size_t row = base + t0 + tt;
            dt_s[tt][j] = dt[row * DI + d0 + j];
            xc_s[tt][j] = xc[row * DI + d0 + j];
            z_s[tt][j]  = xz[row * (2*DI) + DI + d0 + j];
            B_s[tt][j]  = xdbl[row * XPROJ_N + DR + j];
            C_s[tt][j]  = xdbl[row * XPROJ_N + DR + DS + j];
        }
        __syncthreads();
        for (int t = 0; t < CH; t++) {
            float dtv = dt_s[t][dl];
            float xcv = xc_s[t][dl];
            float dA  = __expf(A_dn * dtv);
            s = fmaf(dA, s, dtv * xcv * B_s[t][n]);
            float p = s * C_s[t][n];
            p += __shfl_xor_sync(0xffffffffu, p, 8, 16);
            p += __shfl_xor_sync(0xffffffffu, p, 4, 16);
            p += __shfl_xor_sync(0xffffffffu, p, 2, 16);
            p += __shfl_xor_sync(0xffffffffu, p, 1, 16);
            if (n == 0) {
                float zv = z_s[t][dl];
                float sil = zv / (1.f + __expf(-zv));
                y_s[t][dl] = (p + Dpd * xcv) * sil;
            }
        }
        __syncthreads();
#pragma unroll
        for (int i = 0; i < 4; i++) {
            int e = tid + i*256; int tt = e >> 4, j = e & 15;
            y[(base + t0 + tt) * DI + d0 + j] = y_s[tt][j];
        }
        __syncthreads();
    }
}

// ---------------------------------------------------------------------------
// Launch
// ---------------------------------------------------------------------------
extern "C" void kernel_launch(void* const* d_in, const int* in_sizes, int n_in,
                              void* d_out, int out_size)
{
    const float* x      = (const float*)d_in[0];
    const float* ln_g   = (const float*)d_in[1];
    const float* ln_b   = (const float*)d_in[2];
    const float* W_in   = (const float*)d_in[3];
    const float* conv_w = (const float*)d_in[4];
    const float* conv_b = (const float*)d_in[5];
    const float* W_xprj = (const float*)d_in[6];
    const float* W_dt   = (const float*)d_in[7];
    const float* b_dt   = (const float*)d_in[8];
    const float* A_log  = (const float*)d_in[9];
    const float* Dp     = (const float*)d_in[10];
    const float* W_out  = (const float*)d_in[11];
    float* out = (float*)d_out;

    float *h, *xz, *xc, *xdbl, *xdblp, *dt, *y;
    cudaGetSymbolAddress((void**)&h,     g_h);
    cudaGetSymbolAddress((void**)&xz,    g_xz);
    cudaGetSymbolAddress((void**)&xc,    g_xc);
    cudaGetSymbolAddress((void**)&xdbl,  g_xdbl);
    cudaGetSymbolAddress((void**)&xdblp, g_xdbl_part);
    cudaGetSymbolAddress((void**)&dt,    g_dt);
    cudaGetSymbolAddress((void**)&y,     g_y);

    cudaFuncSetAttribute(gemm_mma_kernel<0>,
        cudaFuncAttributeMaxDynamicSharedMemorySize, GEMM_SMEM_BYTES);
    cudaFuncSetAttribute(gemm_mma_kernel<1>,
        cudaFuncAttributeMaxDynamicSharedMemorySize, GEMM_SMEM_BYTES);
    cudaFuncSetAttribute(gemm_mma_kernel<2>,
        cudaFuncAttributeMaxDynamicSharedMemorySize, GEMM_SMEM_BYTES);

    // 1. LayerNorm
    ln_kernel<<<TOK, 256>>>(x, ln_g, ln_b, h);

    // 2. xz = h @ W_in^T   (2048 x 3072 x 768)
    gemm_mma_kernel<0><<<dim3(2*DI/128, TOK/128, 1), 256, GEMM_SMEM_BYTES>>>(
        h, DM, W_in, DM, xz, 2*DI, nullptr, 2*DI, DM, DM, 0);

    // 3. depthwise conv + silu -> xc
    conv_silu_kernel<<<(TOK*DI)/256, 256>>>(xz, conv_w, conv_b, xc);

    // 4. x_dbl = xc @ W_xproj^T  (2048 x 80 x 1536), split-K=8 -> reduce
    gemm_mma_kernel<0><<<dim3(1, TOK/128, KSPLIT), 256, GEMM_SMEM_BYTES>>>(
        xc, DI, W_xprj, DI, xdblp, XPROJ_N, nullptr, XPROJ_N, DI, DI/KSPLIT,
        (size_t)PART_STRIDE);
    reduce_ksplit_kernel<<<(TOK*XPROJ_N)/256, 256>>>(xdblp, xdbl);

    // 5. dt = softplus(dt_r @ W_dt^T + b_dt)  (2048 x 1536 x 48)
    gemm_mma_kernel<1><<<dim3(DI/128, TOK/128, 1), 256, GEMM_SMEM_BYTES>>>(
        xdbl, XPROJ_N, W_dt, DR, dt, DI, b_dt, DI, DR, DR, 0);

    // 6. selective scan -> y (gated)
    scan_kernel<<<dim3(DI/16, BB), 256>>>(dt, xc, xz, xdbl, A_log, Dp, y);

    // 7. out = x + y @ W_out^T  (2048 x 768 x 1536)
    gemm_mma_kernel<2><<<dim3(DM/128, TOK/128, 1), 256, GEMM_SMEM_BYTES>>>(
        y, DI, W_out, DI, out, DM, x, DM, DI, DI, 0);
}

// round 6
// speedup vs baseline: 3.2351x; 1.4697x over previous
#include <cuda_runtime.h>
#include <cuda_bf16.h>
#include <math.h>
#include <stdint.h>

// Shapes (fixed by the problem)
#define BB      2
#define TT_SEQ  1024
#define DM      768
#define DI      1536        // D_INNER
#define DS      16          // D_STATE
#define DR      48          // DT_RANK
#define TOK     (BB*TT_SEQ) // 2048
#define XPROJ_N (DR + 2*DS) // 80
#define KSPLIT  8
#define PART_STRIDE (TOK * XPROJ_N)   // 163840

// -------- device scratch (no allocs allowed) --------
__device__ float g_h        [TOK * DM];
__device__ float g_xz       [TOK * 2 * DI];
__device__ float g_xc       [TOK * DI];
__device__ float g_xdbl     [TOK * XPROJ_N];
__device__ float g_xdbl_part[KSPLIT * PART_STRIDE];
__device__ float g_dt       [TOK * DI];
__device__ float g_y        [TOK * DI];

// ===========================================================================
// Helpers
// ===========================================================================
__device__ __forceinline__ void cp16(uint32_t dst, const void* src, int bytes) {
    asm volatile("cp.async.cg.shared.global [%0], [%1], 16, %2;"
                 :: "r"(dst), "l"(src), "r"(bytes) : "memory");
}
#define CP_COMMIT() asm volatile("cp.async.commit_group;" ::: "memory")
#define CP_WAIT(n)  asm volatile("cp.async.wait_group %0;" :: "n"(n) : "memory")

__device__ __forceinline__ uint32_t smem_u32(const void* p) {
    uint32_t a;
    asm("{ .reg .u64 t; cvta.to.shared.u64 t, %1; cvt.u32.u64 %0, t; }"
        : "=r"(a) : "l"(p));
    return a;
}

__device__ __forceinline__ void mma_tf32(float* c, const uint32_t* a, const uint32_t* b) {
    asm volatile(
        "mma.sync.aligned.m16n8k8.row.col.f32.tf32.tf32.f32 "
        "{%0,%1,%2,%3}, {%4,%5,%6,%7}, {%8,%9}, {%0,%1,%2,%3};"
        : "+f"(c[0]), "+f"(c[1]), "+f"(c[2]), "+f"(c[3])
        : "r"(a[0]), "r"(a[1]), "r"(a[2]), "r"(a[3]), "r"(b[0]), "r"(b[1]));
}

__device__ __forceinline__ float softplus_f(float v) {
    return (v > 20.f) ? v : __logf(1.f + __expf(v));
}
__device__ __forceinline__ float silu_f(float v) {
    return __fdividef(v, 1.f + __expf(-v));
}

// ===========================================================================
// tf32 mma.sync GEMM: C = A(M x K, lda) * B(N x K, ldb)^T
// Block tile 128x128, BK=32, 128 threads = 4 warps (2 M x 2 N), warp 64x64.
// Per ks-step per warp: 32 LDS feeding 32 HMMA (tensor-pipe-bound by design).
// Shared: As[128][36], Bs[128][36] per buffer, 2 buffers (cp.async pipeline).
// Grid: x = N tile, y = M tile, z = K split.
// MODE 0: store. MODE 1: softplus(acc + ep[col]). MODE 2: acc + ep[row*ldc+col].
// Requires M % 128 == 0 (true at all call sites); N, K ragged edges guarded.
// ===========================================================================
#define PITCH 36
#define TILE_ELEMS (128 * PITCH)            // floats per matrix tile
#define BUF_ELEMS  (2 * TILE_ELEMS)         // A + B
#define GEMM_SMEM_BYTES (2 * BUF_ELEMS * 4) // 73728

template<int MODE>
__global__ void __launch_bounds__(128) gemm_mma_kernel(
    const float* __restrict__ A, int lda,
    const float* __restrict__ B, int ldb,
    float* __restrict__ C, int ldc,
    const float* __restrict__ ep,
    int N, int Ktotal, int ksplit, size_t zstride)
{
    extern __shared__ float smem[];
    const int tid = threadIdx.x;
    const int wid = tid >> 5, lid = tid & 31;
    const int g = lid >> 2, tig = lid & 3;
    const int warp_m = (wid & 1) * 64;
    const int warp_n = (wid >> 1) * 64;
    const int m0 = blockIdx.y * 128;
    const int n0 = blockIdx.x * 128;
    const int kbeg = blockIdx.z * ksplit;
    const int kend = min(kbeg + ksplit, Ktotal);
    C += (size_t)blockIdx.z * zstride;

    const uint32_t sbase = smem_u32(smem);

    float acc[4][8][4];
#pragma unroll
    for (int i = 0; i < 4; i++)
#pragma unroll
        for (int j = 0; j < 8; j++)
#pragma unroll
            for (int q = 0; q < 4; q++) acc[i][j][q] = 0.f;

    const int NT = (kend - kbeg + 31) >> 5;

    // tile loader: global -> smem buffer (cp.async, zero-filled edges)
    auto load_tiles = [&](int it, int buf) {
        const int k0 = kbeg + it * 32;
        const uint32_t sA = sbase + (uint32_t)(buf * BUF_ELEMS) * 4;
        const uint32_t sB = sA + (uint32_t)TILE_ELEMS * 4;
#pragma unroll
        for (int j = 0; j < 8; j++) {
            int idx = tid + j * 128;           // 0..1023
            int r = idx >> 3, c4 = (idx & 7) * 4;
            int kk = k0 + c4;
            int bytes = min(max(kend - kk, 0), 4) * 4;
            int ksafe = bytes ? kk : k0;
            // A tile row m0+r (always valid)
            cp16(sA + (uint32_t)(r * PITCH + c4) * 4,
                 A + (size_t)(m0 + r) * lda + ksafe, bytes);
            // B tile row n0+r (guard N)
            int nr = n0 + r;
            int bytesB = (nr < N) ? bytes : 0;
            cp16(sB + (uint32_t)(r * PITCH + c4) * 4,
                 B + (size_t)((nr < N) ? nr : 0) * ldb + ksafe, bytesB);
        }
        CP_COMMIT();
    };

    load_tiles(0, 0);

    for (int it = 0; it < NT; it++) {
        if (it + 1 < NT) { load_tiles(it + 1, (it + 1) & 1); CP_WAIT(1); }
        else             { CP_WAIT(0); }
        __syncthreads();

        const float* As = smem + (it & 1) * BUF_ELEMS;
        const float* Bs = As + TILE_ELEMS;
#pragma unroll
        for (int ks = 0; ks < 4; ks++) {
            const int k = ks * 8;
            uint32_t a[4][4], b[8][2];
#pragma unroll
            for (int ma = 0; ma < 4; ma++) {
                int r = warp_m + ma * 16 + g;
                a[ma][0] = __float_as_uint(As[r * PITCH + k + tig]);
                a[ma][1] = __float_as_uint(As[(r + 8) * PITCH + k + tig]);
                a[ma][2] = __float_as_uint(As[r * PITCH + k + tig + 4]);
                a[ma][3] = __float_as_uint(As[(r + 8) * PITCH + k + tig + 4]);
            }
#pragma unroll
            for (int na = 0; na < 8; na++) {
                int rn = warp_n + na * 8 + g;
                b[na][0] = __float_as_uint(Bs[rn * PITCH + k + tig]);
                b[na][1] = __float_as_uint(Bs[rn * PITCH + k + tig + 4]);
            }
#pragma unroll
            for (int ma = 0; ma < 4; ma++)
#pragma unroll
                for (int na = 0; na < 8; na++)
                    mma_tf32(acc[ma][na], a[ma], b[na]);
        }
        __syncthreads();
    }

    // Epilogue: c0,c1 -> (row g, col tig*2 +0/1); c2,c3 -> row g+8
#pragma unroll
    for (int ma = 0; ma < 4; ma++) {
        int row0 = m0 + warp_m + ma * 16 + g;
#pragma unroll
        for (int na = 0; na < 8; na++) {
            int col = n0 + warp_n + na * 8 + tig * 2;
            if (col < N) {
                float v0 = acc[ma][na][0], v1 = acc[ma][na][1];
                float v2 = acc[ma][na][2], v3 = acc[ma][na][3];
                if (MODE == 1) {
                    v0 = softplus_f(v0 + ep[col]);  v1 = softplus_f(v1 + ep[col+1]);
                    v2 = softplus_f(v2 + ep[col]);  v3 = softplus_f(v3 + ep[col+1]);
                }
                if (MODE == 2) {
                    const float2 e0 = *(const float2*)&ep[(size_t)row0 * ldc + col];
                    const float2 e1 = *(const float2*)&ep[(size_t)(row0+8) * ldc + col];
                    v0 += e0.x; v1 += e0.y; v2 += e1.x; v3 += e1.y;
                }
                *(float2*)&C[(size_t)row0 * ldc + col]       = make_float2(v0, v1);
                *(float2*)&C[(size_t)(row0 + 8) * ldc + col] = make_float2(v2, v3);
            }
        }
    }
}

// ===========================================================================
// Split-K reduction for x_dbl (deterministic)
// ===========================================================================
__global__ void __launch_bounds__(256) reduce_ksplit_kernel(
    const float* __restrict__ part, float* __restrict__ o)
{
    int i = blockIdx.x * 256 + threadIdx.x;
    float s = 0.f;
#pragma unroll
    for (int z = 0; z < KSPLIT; z++) s += part[(size_t)z * PART_STRIDE + i];
    o[i] = s;
}

// ===========================================================================
// Block reduce (256 threads)
// ===========================================================================
__device__ __forceinline__ float blockReduce256(float v, float* sh) {
    __syncthreads();
    int lane = threadIdx.x & 31, w = threadIdx.x >> 5;
#pragma unroll
    for (int o = 16; o; o >>= 1) v += __shfl_xor_sync(0xffffffffu, v, o);
    if (lane == 0) sh[w] = v;
    __syncthreads();
    float r = sh[0];
#pragma unroll
    for (int i = 1; i < 8; i++) r += sh[i];
    return r;
}

// ---------------------------------------------------------------------------
// LayerNorm
// ---------------------------------------------------------------------------
__global__ void __launch_bounds__(256) ln_kernel(
    const float* __restrict__ x, const float* __restrict__ g,
    const float* __restrict__ bta, float* __restrict__ h)
{
    __shared__ float sh[8];
    int row = blockIdx.x;
    int tid = threadIdx.x;
    const float* xr = x + (size_t)row * DM;
    float v[3]; float sum = 0.f;
#pragma unroll
    for (int i = 0; i < 3; i++) { v[i] = xr[tid + i*256]; sum += v[i]; }
    sum = blockReduce256(sum, sh);
    float mu = sum * (1.f/768.f);
    float q = 0.f;
#pragma unroll
    for (int i = 0; i < 3; i++) { float d = v[i]-mu; q += d*d; }
    q = blockReduce256(q, sh);
    float rs = rsqrtf(q * (1.f/768.f) + 1e-5f);
    float* hr = h + (size_t)row * DM;
#pragma unroll
    for (int i = 0; i < 3; i++) {
        int c = tid + i*256;
        hr[c] = (v[i]-mu) * rs * g[c] + bta[c];
    }
}

// ---------------------------------------------------------------------------
// Depthwise causal conv (width 4) + bias + SiLU
// ---------------------------------------------------------------------------
__global__ void __launch_bounds__(256) conv_silu_kernel(
    const float* __restrict__ xz, const float* __restrict__ w,
    const float* __restrict__ b, float* __restrict__ xc)
{
    int idx = blockIdx.x * 256 + threadIdx.x;
    int d = idx % DI;
    int t = (idx / DI) % TT_SEQ;
    int bb = idx / (DI * TT_SEQ);
    const float* xs = xz + (size_t)bb * TT_SEQ * (2*DI);
    float acc = b[d];
#pragma unroll
    for (int k = 0; k < 4; k++) {
        int tt = t - 3 + k;
        if (tt >= 0) acc = fmaf(w[d*4 + k], xs[(size_t)tt * (2*DI) + d], acc);
    }
    xc[(size_t)(bb * TT_SEQ + t) * DI + d] = silu_f(acc);
}

// ---------------------------------------------------------------------------
// Selective scan (16 channels x 16 states per block), deferred reduction:
// per step only STS p = s*C; the n-sum + D-skip + SiLU gate run as a
// parallel (t,ch) pass per 32-step chunk (no per-step shfl trees).
// ---------------------------------------------------------------------------
__global__ void __launch_bounds__(256) scan_kernel(
    const float* __restrict__ dt, const float* __restrict__ xc,
    const float* __restrict__ xz, const float* __restrict__ xdbl,
    const float* __restrict__ A_log, const float* __restrict__ Dp,
    float* __restrict__ y)
{
    constexpr int CH = 32;
    __shared__ float dt_s[CH][16], xc_s[CH][16], z_s[CH][16];
    __shared__ float B_s[CH][16], C_s[CH][16];
    __shared__ float p_s[CH][16][16];
    __shared__ float Dp_s[16];

    const int b  = blockIdx.y;
    const int d0 = blockIdx.x * 16;
    const int tid = threadIdx.x;
    const int n  = tid & 15;
    const int dl = tid >> 4;
    const int d  = d0 + dl;

    const float A_dn = -__expf(A_log[d * DS + n]);
    if (tid < 16) Dp_s[tid] = Dp[d0 + tid];
    float s = 0.f;
    const size_t base = (size_t)b * TT_SEQ;

    for (int t0 = 0; t0 < TT_SEQ; t0 += CH) {
#pragma unroll
        for (int i = 0; i < 2; i++) {
            int e = tid + i*256; int tt = e >> 4, j = e & 15;
            size_t row = base + t0 + tt;
            dt_s[tt][j] = dt[row * DI + d0 + j];
            xc_s[tt][j] = xc[row * DI + d0 + j];
            z_s[tt][j]  = xz[row * (2*DI) + DI + d0 + j];
            B_s[tt][j]  = xdbl[row * XPROJ_N + DR + j];
            C_s[tt][j]  = xdbl[row * XPROJ_N + DR + DS + j];
        }
        __syncthreads();
#pragma unroll 4
        for (int t = 0; t < CH; t++) {
            float dtv = dt_s[t][dl];
            float xcv = xc_s[t][dl];
            float dA  = __expf(A_dn * dtv);
            s = fmaf(dA, s, dtv * xcv * B_s[t][n]);
            p_s[t][dl][n] = s * C_s[t][n];
        }
        __syncthreads();
#pragma unroll
        for (int i = 0; i < 2; i++) {
            int e = tid + i*256; int tt = e >> 4, ch = e & 15;
            const float4* pp = (const float4*)p_s[tt][ch];
            float4 q0 = pp[0], q1 = pp[1], q2 = pp[2], q3 = pp[3];
            float sum = ((q0.x+q0.y)+(q0.z+q0.w)) + ((q1.x+q1.y)+(q1.z+q1.w))
                      + ((q2.x+q2.y)+(q2.z+q2.w)) + ((q3.x+q3.y)+(q3.z+q3.w));
            float xcv = xc_s[tt][ch];
            float zv  = z_s[tt][ch];
            y[(base + t0 + tt) * DI + d0 + ch] =
                (sum + Dp_s[ch] * xcv) * silu_f(zv);
        }
        __syncthreads();
    }
}

// ---------------------------------------------------------------------------
// Launch
// ---------------------------------------------------------------------------
extern "C" void kernel_launch(void* const* d_in, const int* in_sizes, int n_in,
                              void* d_out, int out_size)
{
    const float* x      = (const float*)d_in[0];
    const float* ln_g   = (const float*)d_in[1];
    const float* ln_b   = (const float*)d_in[2];
    const float* W_in   = (const float*)d_in[3];
    const float* conv_w = (const float*)d_in[4];
    const float* conv_b = (const float*)d_in[5];
    const float* W_xprj = (const float*)d_in[6];
    const float* W_dt   = (const float*)d_in[7];
    const float* b_dt   = (const float*)d_in[8];
    const float* A_log  = (const float*)d_in[9];
    const float* Dp     = (const float*)d_in[10];
    const float* W_out  = (const float*)d_in[11];
    float* out = (float*)d_out;

    float *h, *xz, *xc, *xdbl, *xdblp, *dt, *y;
    cudaGetSymbolAddress((void**)&h,     g_h);
    cudaGetSymbolAddress((void**)&xz,    g_xz);
    cudaGetSymbolAddress((void**)&xc,    g_xc);
    cudaGetSymbolAddress((void**)&xdbl,  g_xdbl);
    cudaGetSymbolAddress((void**)&xdblp, g_xdbl_part);
    cudaGetSymbolAddress((void**)&dt,    g_dt);
    cudaGetSymbolAddress((void**)&y,     g_y);

    cudaFuncSetAttribute(gemm_mma_kernel<0>,
        cudaFuncAttributeMaxDynamicSharedMemorySize, GEMM_SMEM_BYTES);
    cudaFuncSetAttribute(gemm_mma_kernel<1>,
        cudaFuncAttributeMaxDynamicSharedMemorySize, GEMM_SMEM_BYTES);
    cudaFuncSetAttribute(gemm_mma_kernel<2>,
        cudaFuncAttributeMaxDynamicSharedMemorySize, GEMM_SMEM_BYTES);

    // 1. LayerNorm
    ln_kernel<<<TOK, 256>>>(x, ln_g, ln_b, h);

    // 2. xz = h @ W_in^T   (2048 x 3072 x 768)
    gemm_mma_kernel<0><<<dim3(2*DI/128, TOK/128, 1), 128, GEMM_SMEM_BYTES>>>(
        h, DM, W_in, DM, xz, 2*DI, nullptr, 2*DI, DM, DM, 0);

    // 3. depthwise conv + silu -> xc
    conv_silu_kernel<<<(TOK*DI)/256, 256>>>(xz, conv_w, conv_b, xc);

    // 4. x_dbl = xc @ W_xproj^T  (2048 x 80 x 1536), split-K=8 -> reduce
    gemm_mma_kernel<0><<<dim3(1, TOK/128, KSPLIT), 128, GEMM_SMEM_BYTES>>>(
        xc, DI, W_xprj, DI, xdblp, XPROJ_N, nullptr, XPROJ_N, DI, DI/KSPLIT,
        (size_t)PART_STRIDE);
    reduce_ksplit_kernel<<<(TOK*XPROJ_N)/256, 256>>>(xdblp, xdbl);

    // 5. dt = softplus(dt_r @ W_dt^T + b_dt)  (2048 x 1536 x 48)
    gemm_mma_kernel<1><<<dim3(DI/128, TOK/128, 1), 128, GEMM_SMEM_BYTES>>>(
        xdbl, XPROJ_N, W_dt, DR, dt, DI, b_dt, DI, DR, DR, 0);

    // 6. selective scan -> y (gated)
    scan_kernel<<<dim3(DI/16, BB), 256>>>(dt, xc, xz, xdbl, A_log, Dp, y);

    // 7. out = x + y @ W_out^T  (2048 x 768 x 1536)
    gemm_mma_kernel<2><<<dim3(DM/128, TOK/128, 1), 128, GEMM_SMEM_BYTES>>>(
        y, DI, W_out, DI, out, DM, x, DM, DI, DI, 0);
}

// round 7
// speedup vs baseline: 3.7370x; 1.1551x over previous
#include <cuda_runtime.h>
#include <cuda_bf16.h>
#include <math.h>
#include <stdint.h>

// Shapes (fixed by the problem)
#define BB      2
#define TT_SEQ  1024
#define DM      768
#define DI      1536        // D_INNER
#define DS      16          // D_STATE
#define DR      48          // DT_RANK
#define TOK     (BB*TT_SEQ) // 2048
#define XPROJ_N (DR + 2*DS) // 80
#define KSPLIT  8
#define PART_STRIDE (TOK * XPROJ_N)   // 163840

// -------- device scratch (no allocs allowed) --------
__device__ float          g_xz       [TOK * 2 * DI];
__device__ float          g_xc       [TOK * DI];
__device__ float          g_xdbl     [TOK * XPROJ_N];
__device__ float          g_xdbl_part[KSPLIT * PART_STRIDE];
__device__ float          g_dt       [TOK * DI];
// bf16 operand buffers
__device__ __nv_bfloat16  g_h_bf     [TOK * DM];
__device__ __nv_bfloat16  g_xc_bf    [TOK * DI];
__device__ __nv_bfloat16  g_dtr_bf   [TOK * DR];
__device__ __nv_bfloat16  g_y_bf     [TOK * DI];
__device__ __nv_bfloat16  g_Win_bf   [2 * DI * DM];
__device__ __nv_bfloat16  g_Wxp_bf   [XPROJ_N * DI];
__device__ __nv_bfloat16  g_Wdt_bf   [DI * DR];
__device__ __nv_bfloat16  g_Wout_bf  [DM * DI];

// ===========================================================================
// Helpers
// ===========================================================================
__device__ __forceinline__ void cp16(uint32_t dst, const void* src, int bytes) {
    asm volatile("cp.async.cg.shared.global [%0], [%1], 16, %2;"
                 :: "r"(dst), "l"(src), "r"(bytes) : "memory");
}
#define CP_COMMIT() asm volatile("cp.async.commit_group;" ::: "memory")
#define CP_WAIT(n)  asm volatile("cp.async.wait_group %0;" :: "n"(n) : "memory")

__device__ __forceinline__ uint32_t smem_u32(const void* p) {
    uint32_t a;
    asm("{ .reg .u64 t; cvta.to.shared.u64 t, %1; cvt.u32.u64 %0, t; }"
        : "=r"(a) : "l"(p));
    return a;
}

__device__ __forceinline__ void mma_bf16(float* c, const uint32_t* a, const uint32_t* b) {
    asm volatile(
        "mma.sync.aligned.m16n8k16.row.col.f32.bf16.bf16.f32 "
        "{%0,%1,%2,%3}, {%4,%5,%6,%7}, {%8,%9}, {%0,%1,%2,%3};"
        : "+f"(c[0]), "+f"(c[1]), "+f"(c[2]), "+f"(c[3])
        : "r"(a[0]), "r"(a[1]), "r"(a[2]), "r"(a[3]), "r"(b[0]), "r"(b[1]));
}

__device__ __forceinline__ float softplus_f(float v) {
    return (v > 20.f) ? v : __logf(1.f + __expf(v));
}
__device__ __forceinline__ float silu_f(float v) {
    return __fdividef(v, 1.f + __expf(-v));
}

// ===========================================================================
// bf16 mma.sync GEMM: C(fp32) = A(M x K, lda) * B(N x K, ldb)^T
// Block tile 128x128, BK=32 (2 x k16 steps), 128 threads = 4 warps (2Mx2N),
// warp tile 64x64. Smem rows 80B (64B data + 16B pad): fragment LDS bank
// pattern (20g+tig)%32 is conflict-free; 16B alignment kept for cp.async.
// Grid: x = N tile, y = M tile, z = K split.
// MODE 0: store. MODE 1: softplus(acc + ep[col]). MODE 2: acc + ep[row*ldc+col].
// ===========================================================================
#define PITCHB 80                            // bytes per smem row
#define TILE_B (128 * PITCHB)                // 10240 bytes per matrix tile
#define BUF_B  (2 * TILE_B)                  // A + B per stage
#define GEMM_SMEM_BYTES (2 * BUF_B)          // 40960

template<int MODE>
__global__ void __launch_bounds__(128, 2) gemm_mma_kernel(
    const __nv_bfloat16* __restrict__ A, int lda,
    const __nv_bfloat16* __restrict__ B, int ldb,
    float* __restrict__ C, int ldc,
    const float* __restrict__ ep,
    int N, int Ktotal, int ksplit, size_t zstride)
{
    extern __shared__ char smem[];
    const int tid = threadIdx.x;
    const int wid = tid >> 5, lid = tid & 31;
    const int g = lid >> 2, tig = lid & 3;
    const int warp_m = (wid & 1) * 64;
    const int warp_n = (wid >> 1) * 64;
    const int m0 = blockIdx.y * 128;
    const int n0 = blockIdx.x * 128;
    const int kbeg = blockIdx.z * ksplit;
    const int kend = min(kbeg + ksplit, Ktotal);
    C += (size_t)blockIdx.z * zstride;

    const uint32_t sbase = smem_u32(smem);

    float acc[4][8][4];
#pragma unroll
    for (int i = 0; i < 4; i++)
#pragma unroll
        for (int j = 0; j < 8; j++)
#pragma unroll
            for (int q = 0; q < 4; q++) acc[i][j][q] = 0.f;

    const int NT = (kend - kbeg + 31) >> 5;

    // tile loader: global bf16 -> smem buffer (cp.async, zero-filled edges)
    auto load_tiles = [&](int it, int buf) {
        const int k0 = kbeg + it * 32;
        const uint32_t sA = sbase + (uint32_t)buf * BUF_B;
        const uint32_t sB = sA + TILE_B;
#pragma unroll
        for (int j = 0; j < 4; j++) {
            int idx = tid + j * 128;           // 0..511
            int r = idx >> 2, c8 = (idx & 3) * 8;
            int kk = k0 + c8;
            int bytes = min(max(kend - kk, 0), 8) * 2;
            int ksafe = bytes ? kk : k0;
            cp16(sA + (uint32_t)(r * PITCHB + c8 * 2),
                 A + (size_t)(m0 + r) * lda + ksafe, bytes);
            int nr = n0 + r;
            int bytesB = (nr < N) ? bytes : 0;
            cp16(sB + (uint32_t)(r * PITCHB + c8 * 2),
                 B + (size_t)((nr < N) ? nr : 0) * ldb + ksafe, bytesB);
        }
        CP_COMMIT();
    };

    load_tiles(0, 0);

    for (int it = 0; it < NT; it++) {
        if (it + 1 < NT) { load_tiles(it + 1, (it + 1) & 1); CP_WAIT(1); }
        else             { CP_WAIT(0); }
        __syncthreads();

        const char* As = smem + (it & 1) * BUF_B;
        const char* Bs = As + TILE_B;
#pragma unroll
        for (int ks = 0; ks < 2; ks++) {
            const int kb = (ks * 16 + 2 * tig) * 2;   // byte offset of k=16ks+2tig
            uint32_t a[4][4], b[8][2];
#pragma unroll
            for (int ma = 0; ma < 4; ma++) {
                int r = warp_m + ma * 16 + g;
                a[ma][0] = *(const uint32_t*)(As + r * PITCHB + kb);
                a[ma][1] = *(const uint32_t*)(As + (r + 8) * PITCHB + kb);
                a[ma][2] = *(const uint32_t*)(As + r * PITCHB + kb + 16);
                a[ma][3] = *(const uint32_t*)(As + (r + 8) * PITCHB + kb + 16);
            }
#pragma unroll
            for (int na = 0; na < 8; na++) {
                int rn = warp_n + na * 8 + g;
                b[na][0] = *(const uint32_t*)(Bs + rn * PITCHB + kb);
                b[na][1] = *(const uint32_t*)(Bs + rn * PITCHB + kb + 16);
            }
#pragma unroll
            for (int ma = 0; ma < 4; ma++)
#pragma unroll
                for (int na = 0; na < 8; na++)
                    mma_bf16(acc[ma][na], a[ma], b[na]);
        }
        __syncthreads();
    }

    // Epilogue: c0,c1 -> (row g, col tig*2 +0/1); c2,c3 -> row g+8
#pragma unroll
    for (int ma = 0; ma < 4; ma++) {
        int row0 = m0 + warp_m + ma * 16 + g;
#pragma unroll
        for (int na = 0; na < 8; na++) {
            int col = n0 + warp_n + na * 8 + tig * 2;
            if (col < N) {
                float v0 = acc[ma][na][0], v1 = acc[ma][na][1];
                float v2 = acc[ma][na][2], v3 = acc[ma][na][3];
                if (MODE == 1) {
                    v0 = softplus_f(v0 + ep[col]);  v1 = softplus_f(v1 + ep[col+1]);
                    v2 = softplus_f(v2 + ep[col]);  v3 = softplus_f(v3 + ep[col+1]);
                }
                if (MODE == 2) {
                    const float2 e0 = *(const float2*)&ep[(size_t)row0 * ldc + col];
                    const float2 e1 = *(const float2*)&ep[(size_t)(row0+8) * ldc + col];
                    v0 += e0.x; v1 += e0.y; v2 += e1.x; v3 += e1.y;
                }
                *(float2*)&C[(size_t)row0 * ldc + col]       = make_float2(v0, v1);
                *(float2*)&C[(size_t)(row0 + 8) * ldc + col] = make_float2(v2, v3);
            }
        }
    }
}

// ===========================================================================
// fp32 -> bf16 conversion (vectorized), for weights
// ===========================================================================
__global__ void __launch_bounds__(256) cvt4_kernel(
    const float4* __restrict__ a, __nv_bfloat162* __restrict__ o, int n4)
{
    int i = blockIdx.x * 256 + threadIdx.x;
    if (i < n4) {
        float4 v = a[i];
        o[2*i]   = __floats2bfloat162_rn(v.x, v.y);
        o[2*i+1] = __floats2bfloat162_rn(v.z, v.w);
    }
}

// ===========================================================================
// Split-K reduction for x_dbl; also emits bf16 dt_r slice (cols 0..47)
// ===========================================================================
__global__ void __launch_bounds__(256) reduce_ksplit_kernel(
    const float* __restrict__ part, float* __restrict__ o,
    __nv_bfloat16* __restrict__ dtr_bf)
{
    int i = blockIdx.x * 256 + threadIdx.x;
    float s = 0.f;
#pragma unroll
    for (int z = 0; z < KSPLIT; z++) s += part[(size_t)z * PART_STRIDE + i];
    o[i] = s;
    int row = i / XPROJ_N, col = i - row * XPROJ_N;
    if (col < DR) dtr_bf[row * DR + col] = __float2bfloat16(s);
}

// ===========================================================================
// Block reduce (256 threads)
// ===========================================================================
__device__ __forceinline__ float blockReduce256(float v, float* sh) {
    __syncthreads();
    int lane = threadIdx.x & 31, w = threadIdx.x >> 5;
#pragma unroll
    for (int o = 16; o; o >>= 1) v += __shfl_xor_sync(0xffffffffu, v, o);
    if (lane == 0) sh[w] = v;
    __syncthreads();
    float r = sh[0];
#pragma unroll
    for (int i = 1; i < 8; i++) r += sh[i];
    return r;
}

// ---------------------------------------------------------------------------
// LayerNorm -> bf16 h (only consumer is GEMM1)
// ---------------------------------------------------------------------------
__global__ void __launch_bounds__(256) ln_kernel(
    const float* __restrict__ x, const float* __restrict__ g,
    const float* __restrict__ bta, __nv_bfloat16* __restrict__ h)
{
    __shared__ float sh[8];
    int row = blockIdx.x;
    int tid = threadIdx.x;
    const float* xr = x + (size_t)row * DM;
    float v[3]; float sum = 0.f;
#pragma unroll
    for (int i = 0; i < 3; i++) { v[i] = xr[tid + i*256]; sum += v[i]; }
    sum = blockReduce256(sum, sh);
    float mu = sum * (1.f/768.f);
    float q = 0.f;
#pragma unroll
    for (int i = 0; i < 3; i++) { float d = v[i]-mu; q += d*d; }
    q = blockReduce256(q, sh);
    float rs = rsqrtf(q * (1.f/768.f) + 1e-5f);
    __nv_bfloat16* hr = h + (size_t)row * DM;
#pragma unroll
    for (int i = 0; i < 3; i++) {
        int c = tid + i*256;
        hr[c] = __float2bfloat16((v[i]-mu) * rs * g[c] + bta[c]);
    }
}

// ---------------------------------------------------------------------------
// Depthwise causal conv (width 4) + bias + SiLU -> xc fp32 (scan) + bf16 (GEMM)
// ---------------------------------------------------------------------------
__global__ void __launch_bounds__(256) conv_silu_kernel(
    const float* __restrict__ xz, const float* __restrict__ w,
    const float* __restrict__ b, float* __restrict__ xc,
    __nv_bfloat16* __restrict__ xc_bf)
{
    int idx = blockIdx.x * 256 + threadIdx.x;
    int d = idx % DI;
    int t = (idx / DI) % TT_SEQ;
    int bb = idx / (DI * TT_SEQ);
    const float* xs = xz + (size_t)bb * TT_SEQ * (2*DI);
    float acc = b[d];
#pragma unroll
    for (int k = 0; k < 4; k++) {
        int tt = t - 3 + k;
        if (tt >= 0) acc = fmaf(w[d*4 + k], xs[(size_t)tt * (2*DI) + d], acc);
    }
    float s = silu_f(acc);
    size_t o = (size_t)(bb * TT_SEQ + t) * DI + d;
    xc[o] = s;
    xc_bf[o] = __float2bfloat16(s);
}

// ---------------------------------------------------------------------------
// Selective scan (16 channels x 16 states per block), deferred reduction.
// Output y emitted as bf16 (only consumer is GEMM4).
// ---------------------------------------------------------------------------
__global__ void __launch_bounds__(256) scan_kernel(
    const float* __restrict__ dt, const float* __restrict__ xc,
    const float* __restrict__ xz, const float* __restrict__ xdbl,
    const float* __restrict__ A_log, const float* __restrict__ Dp,
    __nv_bfloat16* __restrict__ y)
{
    constexpr int CH = 32;
    __shared__ float dt_s[CH][16], xc_s[CH][16], z_s[CH][16];
    __shared__ float B_s[CH][16], C_s[CH][16];
    __shared__ float p_s[CH][16][16];
    __shared__ float Dp_s[16];

    const int b  = blockIdx.y;
    const int d0 = blockIdx.x * 16;
    const int tid = threadIdx.x;
    const int n  = tid & 15;
    const int dl = tid >> 4;
    const int d  = d0 + dl;

    const float A_dn = -__expf(A_log[d * DS + n]);
    if (tid < 16) Dp_s[tid] = Dp[d0 + tid];
    float s = 0.f;
    const size_t base = (size_t)b * TT_SEQ;

    for (int t0 = 0; t0 < TT_SEQ; t0 += CH) {
#pragma unroll
        for (int i = 0; i < 2; i++) {
            int e = tid + i*256; int tt = e >> 4, j = e & 15;
            size_t row = base + t0 + tt;
            dt_s[tt][j] = dt[row * DI + d0 + j];
            xc_s[tt][j] = xc[row * DI + d0 + j];
            z_s[tt][j]  = xz[row * (2*DI) + DI + d0 + j];
            B_s[tt][j]  = xdbl[row * XPROJ_N + DR + j];
            C_s[tt][j]  = xdbl[row * XPROJ_N + DR + DS + j];
        }
        __syncthreads();
#pragma unroll 4
        for (int t = 0; t < CH; t++) {
            float dtv = dt_s[t][dl];
            float xcv = xc_s[t][dl];
            float dA  = __expf(A_dn * dtv);
            s = fmaf(dA, s, dtv * xcv * B_s[t][n]);
            p_s[t][dl][n] = s * C_s[t][n];
        }
        __syncthreads();
#pragma unroll
        for (int i = 0; i < 2; i++) {
            int e = tid + i*256; int tt = e >> 4, ch = e & 15;
            const float4* pp = (const float4*)p_s[tt][ch];
            float4 q0 = pp[0], q1 = pp[1], q2 = pp[2], q3 = pp[3];
            float sum = ((q0.x+q0.y)+(q0.z+q0.w)) + ((q1.x+q1.y)+(q1.z+q1.w))
                      + ((q2.x+q2.y)+(q2.z+q2.w)) + ((q3.x+q3.y)+(q3.z+q3.w));
            float xcv = xc_s[tt][ch];
            float zv  = z_s[tt][ch];
            y[(base + t0 + tt) * DI + d0 + ch] =
                __float2bfloat16((sum + Dp_s[ch] * xcv) * silu_f(zv));
        }
        __syncthreads();
    }
}

// ---------------------------------------------------------------------------
// Launch
// ---------------------------------------------------------------------------
extern "C" void kernel_launch(void* const* d_in, const int* in_sizes, int n_in,
                              void* d_out, int out_size)
{
    const float* x      = (const float*)d_in[0];
    const float* ln_g   = (const float*)d_in[1];
    const float* ln_b   = (const float*)d_in[2];
    const float* W_in   = (const float*)d_in[3];
    const float* conv_w = (const float*)d_in[4];
    const float* conv_b = (const float*)d_in[5];
    const float* W_xprj = (const float*)d_in[6];
    const float* W_dt   = (const float*)d_in[7];
    const float* b_dt   = (const float*)d_in[8];
    const float* A_log  = (const float*)d_in[9];
    const float* Dp     = (const float*)d_in[10];
    const float* W_out  = (const float*)d_in[11];
    float* out = (float*)d_out;

    float *xz, *xc, *xdbl, *xdblp, *dt;
    __nv_bfloat16 *h_bf, *xc_bf, *dtr_bf, *y_bf, *Win_bf, *Wxp_bf, *Wdt_bf, *Wout_bf;
    cudaGetSymbolAddress((void**)&xz,      g_xz);
    cudaGetSymbolAddress((void**)&xc,      g_xc);
    cudaGetSymbolAddress((void**)&xdbl,    g_xdbl);
    cudaGetSymbolAddress((void**)&xdblp,   g_xdbl_part);
    cudaGetSymbolAddress((void**)&dt,      g_dt);
    cudaGetSymbolAddress((void**)&h_bf,    g_h_bf);
    cudaGetSymbolAddress((void**)&xc_bf,   g_xc_bf);
    cudaGetSymbolAddress((void**)&dtr_bf,  g_dtr_bf);
    cudaGetSymbolAddress((void**)&y_bf,    g_y_bf);
    cudaGetSymbolAddress((void**)&Win_bf,  g_Win_bf);
    cudaGetSymbolAddress((void**)&Wxp_bf,  g_Wxp_bf);
    cudaGetSymbolAddress((void**)&Wdt_bf,  g_Wdt_bf);
    cudaGetSymbolAddress((void**)&Wout_bf, g_Wout_bf);

    cudaFuncSetAttribute(gemm_mma_kernel<0>,
        cudaFuncAttributeMaxDynamicSharedMemorySize, GEMM_SMEM_BYTES);
    cudaFuncSetAttribute(gemm_mma_kernel<1>,
        cudaFuncAttributeMaxDynamicSharedMemorySize, GEMM_SMEM_BYTES);
    cudaFuncSetAttribute(gemm_mma_kernel<2>,
        cudaFuncAttributeMaxDynamicSharedMemorySize, GEMM_SMEM_BYTES);

    // 0. weight conversions (fp32 -> bf16)
    cvt4_kernel<<<(2*DI*DM/4 + 255)/256, 256>>>(
        (const float4*)W_in,  (__nv_bfloat162*)Win_bf,  2*DI*DM/4);
    cvt4_kernel<<<(XPROJ_N*DI/4 + 255)/256, 256>>>(
        (const float4*)W_xprj,(__nv_bfloat162*)Wxp_bf,  XPROJ_N*DI/4);
    cvt4_kernel<<<(DI*DR/4 + 255)/256, 256>>>(
        (const float4*)W_dt,  (__nv_bfloat162*)Wdt_bf,  DI*DR/4);
    cvt4_kernel<<<(DM*DI/4 + 255)/256, 256>>>(
        (const float4*)W_out, (__nv_bfloat162*)Wout_bf, DM*DI/4);

    // 1. LayerNorm -> bf16
    ln_kernel<<<TOK, 256>>>(x, ln_g, ln_b, h_bf);

    // 2. xz = h @ W_in^T   (2048 x 3072 x 768)
    gemm_mma_kernel<0><<<dim3(2*DI/128, TOK/128, 1), 128, GEMM_SMEM_BYTES>>>(
        h_bf, DM, Win_bf, DM, xz, 2*DI, nullptr, 2*DI, DM, DM, 0);

    // 3. depthwise conv + silu -> xc (fp32 + bf16)
    conv_silu_kernel<<<(TOK*DI)/256, 256>>>(xz, conv_w, conv_b, xc, xc_bf);

    // 4. x_dbl = xc @ W_xproj^T  (2048 x 80 x 1536), split-K=8 -> reduce
    gemm_mma_kernel<0><<<dim3(1, TOK/128, KSPLIT), 128, GEMM_SMEM_BYTES>>>(
        xc_bf, DI, Wxp_bf, DI, xdblp, XPROJ_N, nullptr, XPROJ_N, DI, DI/KSPLIT,
        (size_t)PART_STRIDE);
    reduce_ksplit_kernel<<<(TOK*XPROJ_N)/256, 256>>>(xdblp, xdbl, dtr_bf);

    // 5. dt = softplus(dt_r @ W_dt^T + b_dt)  (2048 x 1536 x 48)
    gemm_mma_kernel<1><<<dim3(DI/128, TOK/128, 1), 128, GEMM_SMEM_BYTES>>>(
        dtr_bf, DR, Wdt_bf, DR, dt, DI, b_dt, DI, DR, DR, 0);

    // 6. selective scan -> y (gated, bf16)
    scan_kernel<<<dim3(DI/16, BB), 256>>>(dt, xc, xz, xdbl, A_log, Dp, y_bf);

    // 7. out = x + y @ W_out^T  (2048 x 768 x 1536)
    gemm_mma_kernel<2><<<dim3(DM/128, TOK/128, 1), 128, GEMM_SMEM_BYTES>>>(
        y_bf, DI, Wout_bf, DI, out, DM, x, DM, DI, DI, 0);
}

// round 8
// speedup vs baseline: 4.0119x; 1.0735x over previous
#include <cuda_runtime.h>
#include <cuda_bf16.h>
#include <math.h>
#include <stdint.h>

// Shapes (fixed by the problem)
#define BB      2
#define TT_SEQ  1024
#define DM      768
#define DI      1536        // D_INNER
#define DS      16          // D_STATE
#define DR      48          // DT_RANK
#define TOK     (BB*TT_SEQ) // 2048
#define XPROJ_N (DR + 2*DS) // 80
#define KSPLIT  8
#define PART_STRIDE (TOK * XPROJ_N)   // 163840

// -------- device scratch (no allocs allowed) --------
__device__ __nv_bfloat16  g_xz       [TOK * 2 * DI];   // bf16 now
__device__ float          g_xc       [TOK * DI];
__device__ float          g_xdbl     [TOK * XPROJ_N];
__device__ float          g_xdbl_part[KSPLIT * PART_STRIDE];
__device__ float          g_dt       [TOK * DI];
__device__ __nv_bfloat16  g_h_bf     [TOK * DM];
__device__ __nv_bfloat16  g_xc_bf    [TOK * DI];
__device__ __nv_bfloat16  g_dtr_bf   [TOK * DR];
__device__ __nv_bfloat16  g_y_bf     [TOK * DI];
__device__ __nv_bfloat16  g_Win_bf   [2 * DI * DM];
__device__ __nv_bfloat16  g_Wxp_bf   [XPROJ_N * DI];
__device__ __nv_bfloat16  g_Wdt_bf   [DI * DR];
__device__ __nv_bfloat16  g_Wout_bf  [DM * DI];

// ===========================================================================
// Helpers
// ===========================================================================
__device__ __forceinline__ void cp16(uint32_t dst, const void* src, int bytes) {
    asm volatile("cp.async.cg.shared.global [%0], [%1], 16, %2;"
                 :: "r"(dst), "l"(src), "r"(bytes) : "memory");
}
#define CP_COMMIT() asm volatile("cp.async.commit_group;" ::: "memory")
#define CP_WAIT(n)  asm volatile("cp.async.wait_group %0;" :: "n"(n) : "memory")

__device__ __forceinline__ uint32_t smem_u32(const void* p) {
    uint32_t a;
    asm("{ .reg .u64 t; cvta.to.shared.u64 t, %1; cvt.u32.u64 %0, t; }"
        : "=r"(a) : "l"(p));
    return a;
}

__device__ __forceinline__ void mma_bf16(float* c, const uint32_t* a, const uint32_t* b) {
    asm volatile(
        "mma.sync.aligned.m16n8k16.row.col.f32.bf16.bf16.f32 "
        "{%0,%1,%2,%3}, {%4,%5,%6,%7}, {%8,%9}, {%0,%1,%2,%3};"
        : "+f"(c[0]), "+f"(c[1]), "+f"(c[2]), "+f"(c[3])
        : "r"(a[0]), "r"(a[1]), "r"(a[2]), "r"(a[3]), "r"(b[0]), "r"(b[1]));
}

__device__ __forceinline__ void ldsm_x4(uint32_t* r, uint32_t addr) {
    asm volatile("ldmatrix.sync.aligned.m8n8.x4.shared.b16 {%0,%1,%2,%3}, [%4];"
        : "=r"(r[0]), "=r"(r[1]), "=r"(r[2]), "=r"(r[3]) : "r"(addr));
}

__device__ __forceinline__ float softplus_f(float v) {
    return (v > 20.f) ? v : __logf(1.f + __expf(v));
}
__device__ __forceinline__ float silu_f(float v) {
    return __fdividef(v, 1.f + __expf(-v));
}

// ===========================================================================
// bf16 mma.sync GEMM with ldmatrix fragment loads.
// C = A(M x K, lda) * B(N x K, ldb)^T. Block tile 128x128, BK=32,
// 128 threads = 4 warps (2Mx2N), warp tile 64x64. Smem rows 80B.
// MODE 0: store bf16. MODE 1: softplus(+ep[col]) fp32.
// MODE 2: +ep[row*ldc+col] fp32. MODE 3: store fp32.
// ===========================================================================
#define PITCHB 80
#define TILE_B (128 * PITCHB)
#define BUF_B  (2 * TILE_B)
#define GEMM_SMEM_BYTES (2 * BUF_B)          // 40960

template<int MODE>
__global__ void __launch_bounds__(128, 2) gemm_mma_kernel(
    const __nv_bfloat16* __restrict__ A, int lda,
    const __nv_bfloat16* __restrict__ B, int ldb,
    void* __restrict__ Cv, int ldc,
    const float* __restrict__ ep,
    int N, int Ktotal, int ksplit, size_t zstride)
{
    extern __shared__ char smem[];
    const int tid = threadIdx.x;
    const int wid = tid >> 5, lid = tid & 31;
    const int g = lid >> 2, tig = lid & 3;
    const int warp_m = (wid & 1) * 64;
    const int warp_n = (wid >> 1) * 64;
    const int m0 = blockIdx.y * 128;
    const int n0 = blockIdx.x * 128;
    const int kbeg = blockIdx.z * ksplit;
    const int kend = min(kbeg + ksplit, Ktotal);

    const uint32_t sbase = smem_u32(smem);
    // ldmatrix lane-address offsets (within a tile)
    const uint32_t aoff = (uint32_t)((warp_m + (lid & 15)) * PITCHB + ((lid >> 4) << 4));
    const uint32_t boff = (uint32_t)((warp_n + (lid & 7) + ((lid >> 4) & 1) * 8) * PITCHB
                                     + ((lid >> 3) & 1) * 16);

    float acc[4][8][4];
#pragma unroll
    for (int i = 0; i < 4; i++)
#pragma unroll
        for (int j = 0; j < 8; j++)
#pragma unroll
            for (int q = 0; q < 4; q++) acc[i][j][q] = 0.f;

    const int NT = (kend - kbeg + 31) >> 5;

    auto load_tiles = [&](int it, int buf) {
        const int k0 = kbeg + it * 32;
        const uint32_t sA = sbase + (uint32_t)buf * BUF_B;
        const uint32_t sB = sA + TILE_B;
#pragma unroll
        for (int j = 0; j < 4; j++) {
            int idx = tid + j * 128;           // 0..511
            int r = idx >> 2, c8 = (idx & 3) * 8;
            int kk = k0 + c8;
            int bytes = min(max(kend - kk, 0), 8) * 2;
            int ksafe = bytes ? kk : k0;
            cp16(sA + (uint32_t)(r * PITCHB + c8 * 2),
                 A + (size_t)(m0 + r) * lda + ksafe, bytes);
            int nr = n0 + r;
            int bytesB = (nr < N) ? bytes : 0;
            cp16(sB + (uint32_t)(r * PITCHB + c8 * 2),
                 B + (size_t)((nr < N) ? nr : 0) * ldb + ksafe, bytesB);
        }
        CP_COMMIT();
    };

    load_tiles(0, 0);

    for (int it = 0; it < NT; it++) {
        if (it + 1 < NT) { load_tiles(it + 1, (it + 1) & 1); CP_WAIT(1); }
        else             { CP_WAIT(0); }
        __syncthreads();

        const uint32_t sA = sbase + (uint32_t)(it & 1) * BUF_B;
        const uint32_t a_base = sA + aoff;
        const uint32_t b_base = sA + TILE_B + boff;
#pragma unroll
        for (int ks = 0; ks < 2; ks++) {
            uint32_t a[4][4], bb[4][4];
#pragma unroll
            for (int ma = 0; ma < 4; ma++)
                ldsm_x4(a[ma], a_base + (uint32_t)(ma * 16 * PITCHB + ks * 32));
#pragma unroll
            for (int np = 0; np < 4; np++)
                ldsm_x4(bb[np], b_base + (uint32_t)(np * 16 * PITCHB + ks * 32));
#pragma unroll
            for (int ma = 0; ma < 4; ma++)
#pragma unroll
                for (int np = 0; np < 4; np++) {
                    mma_bf16(acc[ma][2*np],   a[ma], &bb[np][0]);
                    mma_bf16(acc[ma][2*np+1], a[ma], &bb[np][2]);
                }
        }
        __syncthreads();
    }

    // Epilogue
#pragma unroll
    for (int ma = 0; ma < 4; ma++) {
        int row0 = m0 + warp_m + ma * 16 + g;
#pragma unroll
        for (int na = 0; na < 8; na++) {
            int col = n0 + warp_n + na * 8 + tig * 2;
            if (col < N) {
                float v0 = acc[ma][na][0], v1 = acc[ma][na][1];
                float v2 = acc[ma][na][2], v3 = acc[ma][na][3];
                if (MODE == 0) {
                    __nv_bfloat16* Cb = (__nv_bfloat16*)Cv;
                    *(__nv_bfloat162*)&Cb[(size_t)row0 * ldc + col] =
                        __floats2bfloat162_rn(v0, v1);
                    *(__nv_bfloat162*)&Cb[(size_t)(row0 + 8) * ldc + col] =
                        __floats2bfloat162_rn(v2, v3);
                } else {
                    float* C = (float*)Cv + (size_t)blockIdx.z * zstride;
                    if (MODE == 1) {
                        v0 = softplus_f(v0 + ep[col]);  v1 = softplus_f(v1 + ep[col+1]);
                        v2 = softplus_f(v2 + ep[col]);  v3 = softplus_f(v3 + ep[col+1]);
                    }
                    if (MODE == 2) {
                        const float2 e0 = *(const float2*)&ep[(size_t)row0 * ldc + col];
                        const float2 e1 = *(const float2*)&ep[(size_t)(row0+8) * ldc + col];
                        v0 += e0.x; v1 += e0.y; v2 += e1.x; v3 += e1.y;
                    }
                    *(float2*)&C[(size_t)row0 * ldc + col]       = make_float2(v0, v1);
                    *(float2*)&C[(size_t)(row0 + 8) * ldc + col] = make_float2(v2, v3);
                }
            }
        }
    }
}

// ===========================================================================
// Single fused fp32 -> bf16 weight conversion (4 segments, 1 launch)
// ===========================================================================
#define S0 (2*DI*DM/4)
#define S1 (XPROJ_N*DI/4)
#define S2 (DI*DR/4)
#define S3 (DM*DI/4)
__global__ void __launch_bounds__(256) cvt_all_kernel(
    const float4* __restrict__ w_in,  __nv_bfloat162* __restrict__ o_in,
    const float4* __restrict__ w_xp,  __nv_bfloat162* __restrict__ o_xp,
    const float4* __restrict__ w_dt,  __nv_bfloat162* __restrict__ o_dt,
    const float4* __restrict__ w_out, __nv_bfloat162* __restrict__ o_out)
{
    int i = blockIdx.x * 256 + threadIdx.x;
    const float4* src; __nv_bfloat162* dst; int j;
    if      (i < S0)            { src = w_in;  dst = o_in;  j = i; }
    else if (i < S0+S1)         { src = w_xp;  dst = o_xp;  j = i - S0; }
    else if (i < S0+S1+S2)      { src = w_dt;  dst = o_dt;  j = i - S0 - S1; }
    else if (i < S0+S1+S2+S3)   { src = w_out; dst = o_out; j = i - S0 - S1 - S2; }
    else return;
    float4 v = src[j];
    dst[2*j]   = __floats2bfloat162_rn(v.x, v.y);
    dst[2*j+1] = __floats2bfloat162_rn(v.z, v.w);
}

// ===========================================================================
// Split-K reduction for x_dbl; also emits bf16 dt_r slice (cols 0..47)
// ===========================================================================
__global__ void __launch_bounds__(256) reduce_ksplit_kernel(
    const float* __restrict__ part, float* __restrict__ o,
    __nv_bfloat16* __restrict__ dtr_bf)
{
    int i = blockIdx.x * 256 + threadIdx.x;
    float s = 0.f;
#pragma unroll
    for (int z = 0; z < KSPLIT; z++) s += part[(size_t)z * PART_STRIDE + i];
    o[i] = s;
    int row = i / XPROJ_N, col = i - row * XPROJ_N;
    if (col < DR) dtr_bf[row * DR + col] = __float2bfloat16(s);
}

// ===========================================================================
// Block reduce (256 threads)
// ===========================================================================
__device__ __forceinline__ float blockReduce256(float v, float* sh) {
    __syncthreads();
    int lane = threadIdx.x & 31, w = threadIdx.x >> 5;
#pragma unroll
    for (int o = 16; o; o >>= 1) v += __shfl_xor_sync(0xffffffffu, v, o);
    if (lane == 0) sh[w] = v;
    __syncthreads();
    float r = sh[0];
#pragma unroll
    for (int i = 1; i < 8; i++) r += sh[i];
    return r;
}

// ---------------------------------------------------------------------------
// LayerNorm -> bf16 h
// ---------------------------------------------------------------------------
__global__ void __launch_bounds__(256) ln_kernel(
    const float* __restrict__ x, const float* __restrict__ g,
    const float* __restrict__ bta, __nv_bfloat16* __restrict__ h)
{
    __shared__ float sh[8];
    int row = blockIdx.x;
    int tid = threadIdx.x;
    const float* xr = x + (size_t)row * DM;
    float v[3]; float sum = 0.f;
#pragma unroll
    for (int i = 0; i < 3; i++) { v[i] = xr[tid + i*256]; sum += v[i]; }
    sum = blockReduce256(sum, sh);
    float mu = sum * (1.f/768.f);
    float q = 0.f;
#pragma unroll
    for (int i = 0; i < 3; i++) { float d = v[i]-mu; q += d*d; }
    q = blockReduce256(q, sh);
    float rs = rsqrtf(q * (1.f/768.f) + 1e-5f);
    __nv_bfloat16* hr = h + (size_t)row * DM;
#pragma unroll
    for (int i = 0; i < 3; i++) {
        int c = tid + i*256;
        hr[c] = __float2bfloat16((v[i]-mu) * rs * g[c] + bta[c]);
    }
}

// ---------------------------------------------------------------------------
// Depthwise causal conv (width 4) + bias + SiLU, 2 channels per thread.
// xz is bf16; writes xc fp32 (scan) + bf16 (GEMM).
// ---------------------------------------------------------------------------
__global__ void __launch_bounds__(256) conv_silu_kernel(
    const __nv_bfloat16* __restrict__ xz, const float* __restrict__ w,
    const float* __restrict__ b, float* __restrict__ xc,
    __nv_bfloat16* __restrict__ xc_bf)
{
    int idx = blockIdx.x * 256 + threadIdx.x;        // over TOK*DI/2
    int d2 = idx % (DI/2);
    int t  = (idx / (DI/2)) % TT_SEQ;
    int bb = idx / ((DI/2) * TT_SEQ);
    int d  = d2 * 2;
    const __nv_bfloat16* xs = xz + (size_t)bb * TT_SEQ * (2*DI);
    const float4 w0 = ((const float4*)w)[d];
    const float4 w1 = ((const float4*)w)[d+1];
    const float2 b2 = *(const float2*)&b[d];
    float a0 = b2.x, a1 = b2.y;
    const float w0k[4] = {w0.x, w0.y, w0.z, w0.w};
    const float w1k[4] = {w1.x, w1.y, w1.z, w1.w};
#pragma unroll
    for (int k = 0; k < 4; k++) {
        int tt = t - 3 + k;
        if (tt >= 0) {
            float2 xv = __bfloat1622float2(
                *(const __nv_bfloat162*)&xs[(size_t)tt * (2*DI) + d]);
            a0 = fmaf(w0k[k], xv.x, a0);
            a1 = fmaf(w1k[k], xv.y, a1);
        }
    }
    float s0 = silu_f(a0), s1 = silu_f(a1);
    size_t o = (size_t)(bb * TT_SEQ + t) * DI + d;
    *(float2*)&xc[o] = make_float2(s0, s1);
    *(__nv_bfloat162*)&xc_bf[o] = __floats2bfloat162_rn(s0, s1);
}

// ---------------------------------------------------------------------------
// Selective scan (16 channels x 16 states per block), deferred reduction.
// z read from bf16 xz; y emitted bf16.
// ---------------------------------------------------------------------------
__global__ void __launch_bounds__(256) scan_kernel(
    const float* __restrict__ dt, const float* __restrict__ xc,
    const __nv_bfloat16* __restrict__ xz, const float* __restrict__ xdbl,
    const float* __restrict__ A_log, const float* __restrict__ Dp,
    __nv_bfloat16* __restrict__ y)
{
    constexpr int CH = 32;
    __shared__ float dt_s[CH][16], xc_s[CH][16], z_s[CH][16];
    __shared__ float B_s[CH][16], C_s[CH][16];
    __shared__ float p_s[CH][16][16];
    __shared__ float Dp_s[16];

    const int b  = blockIdx.y;
    const int d0 = blockIdx.x * 16;
    const int tid = threadIdx.x;
    const int n  = tid & 15;
    const int dl = tid >> 4;
    const int d  = d0 + dl;

    const float A_dn = -__expf(A_log[d * DS + n]);
    if (tid < 16) Dp_s[tid] = Dp[d0 + tid];
    float s = 0.f;
    const size_t base = (size_t)b * TT_SEQ;

    for (int t0 = 0; t0 < TT_SEQ; t0 += CH) {
#pragma unroll
        for (int i = 0; i < 2; i++) {
            int e = tid + i*256; int tt = e >> 4, j = e & 15;
            size_t row = base + t0 + tt;
            dt_s[tt][j] = dt[row * DI + d0 + j];
            xc_s[tt][j] = xc[row * DI + d0 + j];
            z_s[tt][j]  = __bfloat162float(xz[row * (2*DI) + DI + d0 + j]);
            B_s[tt][j]  = xdbl[row * XPROJ_N + DR + j];
            C_s[tt][j]  = xdbl[row * XPROJ_N + DR + DS + j];
        }
        __syncthreads();
#pragma unroll 4
        for (int t = 0; t < CH; t++) {
            float dtv = dt_s[t][dl];
            float xcv = xc_s[t][dl];
            float dA  = __expf(A_dn * dtv);
            s = fmaf(dA, s, dtv * xcv * B_s[t][n]);
            p_s[t][dl][n] = s * C_s[t][n];
        }
        __syncthreads();
#pragma unroll
        for (int i = 0; i < 2; i++) {
            int e = tid + i*256; int tt = e >> 4, ch = e & 15;
            const float4* pp = (const float4*)p_s[tt][ch];
            float4 q0 = pp[0], q1 = pp[1], q2 = pp[2], q3 = pp[3];
            float sum = ((q0.x+q0.y)+(q0.z+q0.w)) + ((q1.x+q1.y)+(q1.z+q1.w))
                      + ((q2.x+q2.y)+(q2.z+q2.w)) + ((q3.x+q3.y)+(q3.z+q3.w));
            float xcv = xc_s[tt][ch];
            float zv  = z_s[tt][ch];
            y[(base + t0 + tt) * DI + d0 + ch] =
                __float2bfloat16((sum + Dp_s[ch] * xcv) * silu_f(zv));
        }
        __syncthreads();
    }
}

// ---------------------------------------------------------------------------
// Launch
// ---------------------------------------------------------------------------
extern "C" void kernel_launch(void* const* d_in, const int* in_sizes, int n_in,
                              void* d_out, int out_size)
{
    const float* x      = (const float*)d_in[0];
    const float* ln_g   = (const float*)d_in[1];
    const float* ln_b   = (const float*)d_in[2];
    const float* W_in   = (const float*)d_in[3];
    const float* conv_w = (const float*)d_in[4];
    const float* conv_b = (const float*)d_in[5];
    const float* W_xprj = (const float*)d_in[6];
    const float* W_dt   = (const float*)d_in[7];
    const float* b_dt   = (const float*)d_in[8];
    const float* A_log  = (const float*)d_in[9];
    const float* Dp     = (const float*)d_in[10];
    const float* W_out  = (const float*)d_in[11];
    float* out = (float*)d_out;

    float *xc, *xdbl, *xdblp, *dt;
    __nv_bfloat16 *xz, *h_bf, *xc_bf, *dtr_bf, *y_bf, *Win_bf, *Wxp_bf, *Wdt_bf, *Wout_bf;
    cudaGetSymbolAddress((void**)&xz,      g_xz);
    cudaGetSymbolAddress((void**)&xc,      g_xc);
    cudaGetSymbolAddress((void**)&xdbl,    g_xdbl);
    cudaGetSymbolAddress((void**)&xdblp,   g_xdbl_part);
    cudaGetSymbolAddress((void**)&dt,      g_dt);
    cudaGetSymbolAddress((void**)&h_bf,    g_h_bf);
    cudaGetSymbolAddress((void**)&xc_bf,   g_xc_bf);
    cudaGetSymbolAddress((void**)&dtr_bf,  g_dtr_bf);
    cudaGetSymbolAddress((void**)&y_bf,    g_y_bf);
    cudaGetSymbolAddress((void**)&Win_bf,  g_Win_bf);
    cudaGetSymbolAddress((void**)&Wxp_bf,  g_Wxp_bf);
    cudaGetSymbolAddress((void**)&Wdt_bf,  g_Wdt_bf);
    cudaGetSymbolAddress((void**)&Wout_bf, g_Wout_bf);

    cudaFuncSetAttribute(gemm_mma_kernel<0>,
        cudaFuncAttributeMaxDynamicSharedMemorySize, GEMM_SMEM_BYTES);
    cudaFuncSetAttribute(gemm_mma_kernel<1>,
        cudaFuncAttributeMaxDynamicSharedMemorySize, GEMM_SMEM_BYTES);
    cudaFuncSetAttribute(gemm_mma_kernel<2>,
        cudaFuncAttributeMaxDynamicSharedMemorySize, GEMM_SMEM_BYTES);
    cudaFuncSetAttribute(gemm_mma_kernel<3>,
        cudaFuncAttributeMaxDynamicSharedMemorySize, GEMM_SMEM_BYTES);

    // 0. weight conversions (single launch)
    cvt_all_kernel<<<(S0+S1+S2+S3 + 255)/256, 256>>>(
        (const float4*)W_in,  (__nv_bfloat162*)Win_bf,
        (const float4*)W_xprj,(__nv_bfloat162*)Wxp_bf,
        (const float4*)W_dt,  (__nv_bfloat162*)Wdt_bf,
        (const float4*)W_out, (__nv_bfloat162*)Wout_bf);

    // 1. LayerNorm -> bf16
    ln_kernel<<<TOK, 256>>>(x, ln_g, ln_b, h_bf);

    // 2. xz = h @ W_in^T  (2048 x 3072 x 768), bf16 out
    gemm_mma_kernel<0><<<dim3(2*DI/128, TOK/128, 1), 128, GEMM_SMEM_BYTES>>>(
        h_bf, DM, Win_bf, DM, xz, 2*DI, nullptr, 2*DI, DM, DM, 0);

    // 3. depthwise conv + silu -> xc (fp32 + bf16)
    conv_silu_kernel<<<(TOK*DI/2)/256, 256>>>(xz, conv_w, conv_b, xc, xc_bf);

    // 4. x_dbl = xc @ W_xproj^T  (2048 x 80 x 1536), split-K=8 -> reduce
    gemm_mma_kernel<3><<<dim3(1, TOK/128, KSPLIT), 128, GEMM_SMEM_BYTES>>>(
        xc_bf, DI, Wxp_bf, DI, xdblp, XPROJ_N, nullptr, XPROJ_N, DI, DI/KSPLIT,
        (size_t)PART_STRIDE);
    reduce_ksplit_kernel<<<(TOK*XPROJ_N)/256, 256>>>(xdblp, xdbl, dtr_bf);

    // 5. dt = softplus(dt_r @ W_dt^T + b_dt)  (2048 x 1536 x 48)
    gemm_mma_kernel<1><<<dim3(DI/128, TOK/128, 1), 128, GEMM_SMEM_BYTES>>>(
        dtr_bf, DR, Wdt_bf, DR, dt, DI, b_dt, DI, DR, DR, 0);

    // 6. selective scan -> y (gated, bf16)
    scan_kernel<<<dim3(DI/16, BB), 256>>>(dt, xc, xz, xdbl, A_log, Dp, y_bf);

    // 7. out = x + y @ W_out^T  (2048 x 768 x 1536)
    gemm_mma_kernel<2><<<dim3(DM/128, TOK/128, 1), 128, GEMM_SMEM_BYTES>>>(
        y_bf, DI, Wout_bf, DI, out, DM, x, DM, DI, DI, 0);
}